// round 10
// baseline (speedup 1.0000x reference)
#include <cuda_runtime.h>

// SuperVoxelLoss: mean( bce_with_logits(x,t) * (1 + 0.5*[(t>0.5) XOR (x>0)]) )
// Persistent single-wave reduction (148 SM x 6 CTAs) with tiered L2 policy:
//   t  (64 MB)        : __ldcg  -> L2-resident across graph replays
//   x[0 .. 5/8)  40 MB: __ldcg  -> also L2-resident (total protected 104 MB
//                                  of the 126 MB L2)
//   x[5/8 .. 1)  24 MB: __ldcs  -> streamed evict-first, never displaces the
//                                  protected set
// Steady state per replay: ~24 MB DRAM + 134 MB L2 -> LTS-bandwidth bound.

#define NTHR 256
#define NBLK 888          // 148 SMs * 6 resident CTAs = exactly one wave

__device__ float g_partials[NBLK];
__device__ unsigned int g_ticket;   // zero-init; last block resets for graph replay

__device__ __forceinline__ float loss_elem(float x, float t) {
    // stable BCEWithLogits: max(x,0) - x*t + log(1 + exp(-|x|))
    float ax = fabsf(x);
    float e  = __expf(-ax);
    float l  = __logf(1.0f + e);
    float loss = fmaxf(x, 0.0f) - x * t + l;
    // pred_bin = (sigmoid(x) > 0.5) <=> (x > 0); masks are XOR of the bins
    bool pb = x > 0.0f;
    bool tb = t > 0.5f;
    float w = (pb != tb) ? 1.5f : 1.0f;
    return loss * w;
}

__device__ __forceinline__ float block_reduce(float v) {
    #pragma unroll
    for (int o = 16; o > 0; o >>= 1)
        v += __shfl_down_sync(0xFFFFFFFFu, v, o);

    __shared__ float s_warp[NTHR / 32];
    if ((threadIdx.x & 31) == 0) s_warp[threadIdx.x >> 5] = v;
    __syncthreads();

    if (threadIdx.x < 32) {
        float w = (threadIdx.x < NTHR / 32) ? s_warp[threadIdx.x] : 0.0f;
        #pragma unroll
        for (int o = 16; o > 0; o >>= 1)
            w += __shfl_down_sync(0xFFFFFFFFu, w, o);
        return w;   // valid in thread 0
    }
    return 0.0f;
}

__global__ void __launch_bounds__(NTHR, 6)
svloss_fused_kernel(const float4* __restrict__ x4,
                    const float4* __restrict__ t4,
                    float* __restrict__ out,
                    int n4, int x_cut, float inv_n) {
    const int stride = NBLK * NTHR;
    const int tid = blockIdx.x * NTHR + threadIdx.x;

    float a0 = 0.0f, a1 = 0.0f, a2 = 0.0f, a3 = 0.0f;

    #pragma unroll 4
    for (int i = tid; i < n4; i += stride) {
        float4 xv = (i < x_cut) ? __ldcg(&x4[i])   // protected head of x
                                : __ldcs(&x4[i]);  // streamed tail of x
        float4 tv = __ldcg(&t4[i]);                // t always protected
        a0 += loss_elem(xv.x, tv.x);
        a1 += loss_elem(xv.y, tv.y);
        a2 += loss_elem(xv.z, tv.z);
        a3 += loss_elem(xv.w, tv.w);
    }

    float bsum = block_reduce((a0 + a1) + (a2 + a3));

    __shared__ bool s_last;
    if (threadIdx.x == 0) {
        g_partials[blockIdx.x] = bsum;
        __threadfence();
        unsigned int c = atomicAdd(&g_ticket, 1u);
        s_last = (c == (unsigned int)gridDim.x - 1u);
    }
    __syncthreads();

    if (s_last) {
        // deterministic fixed-order reduce of all partials
        float v = 0.0f;
        for (int i = threadIdx.x; i < NBLK; i += NTHR)
            v += g_partials[i];
        float total = block_reduce(v);
        if (threadIdx.x == 0) {
            out[0] = total * inv_n;
            g_ticket = 0u;   // reset for next graph replay
        }
    }
}

extern "C" void kernel_launch(void* const* d_in, const int* in_sizes, int n_in,
                              void* d_out, int out_size) {
    const float4* x4 = (const float4*)d_in[0];
    const float4* t4 = (const float4*)d_in[1];
    float* out = (float*)d_out;

    int n = in_sizes[0];          // 16,777,216
    int n4 = n >> 2;              // 4,194,304 float4s per array (64 MB)
    int x_cut = (int)(((long long)n4 * 5) / 8);   // first 40 MB of x cached

    svloss_fused_kernel<<<NBLK, NTHR>>>(x4, t4, out, n4, x_cut, 1.0f / (float)n);
}

// round 11
// speedup vs baseline: 1.1926x; 1.1926x over previous
#include <cuda_runtime.h>

// SuperVoxelLoss: mean( bce_with_logits(x,t) * (1 + 0.5*[(t>0.5) XOR (x>0)]) )
// Persistent single-wave reduction (148 SM x 6 CTAs) with tiered L2 policy:
//   t  (64 MB)        : __ldcg  -> L2-resident across graph replays
//   x[0 .. 1/4) 16 MB : __ldcg  -> also protected (total 80 MB of 126 MB L2,
//                                  46 MB slack -- R10 showed 104 MB thrashes)
//   x[1/4 .. 1) 48 MB : __ldcs  -> streamed evict-first
// Steady state per replay: ~48 MB DRAM + rest from L2.

#define NTHR 256
#define NBLK 888          // 148 SMs * 6 resident CTAs = exactly one wave

__device__ float g_partials[NBLK];
__device__ unsigned int g_ticket;   // zero-init; last block resets for graph replay

__device__ __forceinline__ float loss_elem(float x, float t) {
    // stable BCEWithLogits: max(x,0) - x*t + log(1 + exp(-|x|))
    float ax = fabsf(x);
    float e  = __expf(-ax);
    float l  = __logf(1.0f + e);
    float loss = fmaxf(x, 0.0f) - x * t + l;
    // pred_bin = (sigmoid(x) > 0.5) <=> (x > 0); masks are XOR of the bins
    bool pb = x > 0.0f;
    bool tb = t > 0.5f;
    float w = (pb != tb) ? 1.5f : 1.0f;
    return loss * w;
}

__device__ __forceinline__ float block_reduce(float v) {
    #pragma unroll
    for (int o = 16; o > 0; o >>= 1)
        v += __shfl_down_sync(0xFFFFFFFFu, v, o);

    __shared__ float s_warp[NTHR / 32];
    if ((threadIdx.x & 31) == 0) s_warp[threadIdx.x >> 5] = v;
    __syncthreads();

    if (threadIdx.x < 32) {
        float w = (threadIdx.x < NTHR / 32) ? s_warp[threadIdx.x] : 0.0f;
        #pragma unroll
        for (int o = 16; o > 0; o >>= 1)
            w += __shfl_down_sync(0xFFFFFFFFu, w, o);
        return w;   // valid in thread 0
    }
    return 0.0f;
}

__global__ void __launch_bounds__(NTHR, 6)
svloss_fused_kernel(const float4* __restrict__ x4,
                    const float4* __restrict__ t4,
                    float* __restrict__ out,
                    int n4, int x_cut, float inv_n) {
    const int stride = NBLK * NTHR;
    const int tid = blockIdx.x * NTHR + threadIdx.x;

    float a0 = 0.0f, a1 = 0.0f, a2 = 0.0f, a3 = 0.0f;

    #pragma unroll 4
    for (int i = tid; i < n4; i += stride) {
        float4 xv = (i < x_cut) ? __ldcg(&x4[i])   // protected head of x
                                : __ldcs(&x4[i]);  // streamed tail of x
        float4 tv = __ldcg(&t4[i]);                // t always protected
        a0 += loss_elem(xv.x, tv.x);
        a1 += loss_elem(xv.y, tv.y);
        a2 += loss_elem(xv.z, tv.z);
        a3 += loss_elem(xv.w, tv.w);
    }

    float bsum = block_reduce((a0 + a1) + (a2 + a3));

    __shared__ bool s_last;
    if (threadIdx.x == 0) {
        g_partials[blockIdx.x] = bsum;
        __threadfence();
        unsigned int c = atomicAdd(&g_ticket, 1u);
        s_last = (c == (unsigned int)gridDim.x - 1u);
    }
    __syncthreads();

    if (s_last) {
        // deterministic fixed-order reduce of all partials
        float v = 0.0f;
        for (int i = threadIdx.x; i < NBLK; i += NTHR)
            v += g_partials[i];
        float total = block_reduce(v);
        if (threadIdx.x == 0) {
            out[0] = total * inv_n;
            g_ticket = 0u;   // reset for next graph replay
        }
    }
}

extern "C" void kernel_launch(void* const* d_in, const int* in_sizes, int n_in,
                              void* d_out, int out_size) {
    const float4* x4 = (const float4*)d_in[0];
    const float4* t4 = (const float4*)d_in[1];
    float* out = (float*)d_out;

    int n = in_sizes[0];          // 16,777,216
    int n4 = n >> 2;              // 4,194,304 float4s per array (64 MB)
    int x_cut = n4 >> 2;          // first 16 MB of x protected

    svloss_fused_kernel<<<NBLK, NTHR>>>(x4, t4, out, n4, x_cut, 1.0f / (float)n);
}